// round 1
// baseline (speedup 1.0000x reference)
#include <cuda_runtime.h>

// Problem constants (fixed by the reference)
#define NROWS_TOTAL 65536
#define D 512
#define S 32
#define C 64
#define H 64

#define ROWS 64          // rows per CTA
#define THREADS 256
#define XG_STRIDE (ROWS + 1)   // 65: conflict-free transposed gather tile

// Dynamic smem layout (floats):
//   xgT : C * XG_STRIDE        (64*65 = 4160)   xgT[c*65 + r]
//   ws  : C * H                (4096)           W1[s] staged
//   skp : ROWS                 (64)             per-row skip dot
#define SMEM_FLOATS (C * XG_STRIDE + C * H + ROWS)

__global__ void __launch_bounds__(THREADS, 4)
hybrid_kernel(const float* __restrict__ x,
              const float* __restrict__ skip_w,
              const float* __restrict__ skip_b,
              const float* __restrict__ W1,
              const float* __restrict__ b1,
              const float* __restrict__ W2,
              const float* __restrict__ b2,
              const int*   __restrict__ col_ids,
              float* __restrict__ out)
{
    extern __shared__ float smem[];
    float* xgT = smem;                       // 4160
    float* ws  = smem + C * XG_STRIDE;       // 4096 (16B aligned: 4160*4 = 16640)
    float* skp = ws + C * H;                 // 64

    const int tid     = threadIdx.x;
    const int rowbase = blockIdx.x * ROWS;

    // ---------------- skip: per-row dot x[r] . skip_w (warp per 8 rows) ----
    {
        const int w    = tid >> 5;
        const int lane = tid & 31;
        #pragma unroll
        for (int rr = 0; rr < 8; ++rr) {
            const int r = w * 8 + rr;
            const float4* xrow = (const float4*)(x + (size_t)(rowbase + r) * D);
            const float4* sw4  = (const float4*)skip_w;
            float acc = 0.f;
            #pragma unroll
            for (int j = 0; j < 4; ++j) {
                float4 xv = xrow[j * 32 + lane];
                float4 wv = sw4[j * 32 + lane];
                acc += xv.x * wv.x + xv.y * wv.y + xv.z * wv.z + xv.w * wv.w;
            }
            #pragma unroll
            for (int o = 16; o > 0; o >>= 1)
                acc += __shfl_xor_sync(0xffffffffu, acc, o);
            if (lane == 0) skp[r] = acc;
        }
    }

    // compute-thread identity: 16 row-groups x 16 h-groups
    const int rb  = tid >> 4;        // 0..15 : rows rb*4 .. rb*4+3
    const int hb  = tid & 15;        // 0..15 : cols hb*4 .. hb*4+3
    const int rb4 = rb * 4;
    const int hb4 = hb * 4;

    // gather-thread identity
    const int gcol = tid & 63;       // column slot within segment
    const int gr0  = tid >> 6;       // 0..3

    float rowacc[4] = {0.f, 0.f, 0.f, 0.f};

    for (int s = 0; s < S; ++s) {
        __syncthreads();   // protect xgT/ws reuse across segments (also orders skp)

        // stage W1[s] (4096 floats) via float4
        {
            const float4* w1s = (const float4*)(W1 + (size_t)s * (C * H));
            float4* wsd = (float4*)ws;
            #pragma unroll
            for (int k = 0; k < 4; ++k)
                wsd[tid + k * THREADS] = w1s[tid + k * THREADS];
        }
        // gather xgT[col][r] = x[rowbase + r][col_ids[s][col]]
        {
            const int cid = col_ids[s * C + gcol];
            const float* xc = x + cid;
            float* dst = xgT + gcol * XG_STRIDE;
            #pragma unroll
            for (int k = 0; k < 16; ++k) {
                const int r = gr0 + 4 * k;
                dst[r] = __ldg(xc + (size_t)(rowbase + r) * D);
            }
        }
        __syncthreads();

        // per-thread second-layer params
        float b1v[4], w2v[4];
        #pragma unroll
        for (int j = 0; j < 4; ++j) {
            b1v[j] = b1[s * H + hb4 + j];
            w2v[j] = W2[s * H + hb4 + j];
        }

        // 4x4 register-tiled matvec block: acc[i][j] = sum_c xg[r_i][c] * W1[c][h_j]
        float acc[4][4] = {};
        #pragma unroll 4
        for (int c = 0; c < C; ++c) {
            const float4 wv = *(const float4*)(ws + c * H + hb4);
            const float* xg = xgT + c * XG_STRIDE + rb4;
            const float x0 = xg[0], x1 = xg[1], x2 = xg[2], x3 = xg[3];
            acc[0][0] += x0 * wv.x; acc[0][1] += x0 * wv.y; acc[0][2] += x0 * wv.z; acc[0][3] += x0 * wv.w;
            acc[1][0] += x1 * wv.x; acc[1][1] += x1 * wv.y; acc[1][2] += x1 * wv.z; acc[1][3] += x1 * wv.w;
            acc[2][0] += x2 * wv.x; acc[2][1] += x2 * wv.y; acc[2][2] += x2 * wv.z; acc[2][3] += x2 * wv.w;
            acc[3][0] += x3 * wv.x; acc[3][1] += x3 * wv.y; acc[3][2] += x3 * wv.z; acc[3][3] += x3 * wv.w;
        }

        // fused layer-2: relu(acc + b1) . W2, reduce across the 16 h-threads
        #pragma unroll
        for (int i = 0; i < 4; ++i) {
            float p = 0.f;
            #pragma unroll
            for (int j = 0; j < 4; ++j) {
                const float hv = fmaxf(acc[i][j] + b1v[j], 0.f);
                p += hv * w2v[j];
            }
            p += __shfl_xor_sync(0xffffffffu, p, 8, 16);
            p += __shfl_xor_sync(0xffffffffu, p, 4, 16);
            p += __shfl_xor_sync(0xffffffffu, p, 2, 16);
            p += __shfl_xor_sync(0xffffffffu, p, 1, 16);
            if (hb == 0) rowacc[i] += p;
        }
    }

    // final: skip + skip_b + sum(b2) + segment sum, clipped
    if (hb == 0) {
        float extra = skip_b[0];
        #pragma unroll
        for (int s = 0; s < S; ++s) extra += b2[s];
        #pragma unroll
        for (int i = 0; i < 4; ++i) {
            const int r = rb4 + i;
            float v = skp[r] + extra + rowacc[i];
            v = fminf(fmaxf(v, -20.0f), 20.0f);
            out[rowbase + r] = v;
        }
    }
}

extern "C" void kernel_launch(void* const* d_in, const int* in_sizes, int n_in,
                              void* d_out, int out_size)
{
    const float* x       = (const float*)d_in[0];
    const float* skip_w  = (const float*)d_in[1];
    const float* skip_b  = (const float*)d_in[2];
    const float* W1      = (const float*)d_in[3];
    const float* b1      = (const float*)d_in[4];
    const float* W2      = (const float*)d_in[5];
    const float* b2      = (const float*)d_in[6];
    const int*   col_ids = (const int*)  d_in[7];
    float* out = (float*)d_out;

    const int nrows = in_sizes[0] / D;           // 65536
    const int grid  = nrows / ROWS;              // 1024
    const size_t smem_bytes = SMEM_FLOATS * sizeof(float);  // ~33.3 KB

    hybrid_kernel<<<grid, THREADS, smem_bytes>>>(
        x, skip_w, skip_b, W1, b1, W2, b2, col_ids, out);
}

// round 3
// speedup vs baseline: 1.4220x; 1.4220x over previous
#include <cuda_runtime.h>
#include <cuda_bf16.h>
#include <cstdint>

// Problem constants
#define D 512
#define S 32
#define C 64
#define H 64
#define MROWS 128           // rows per CTA
#define THREADS 256         // 8 warps, warp = 16-row stripe
#define NB 72               // output cols: 64 h + skip col (64) + 7 zero pad
#define NT 9                // n-tiles of 8
#define ASTRIDE 144         // bytes per A row  (72 bf16; 64 used) -> conflict-free
#define BSTRIDE 144         // bytes per B row  (72 bf16)

// smem byte offsets
#define SM_AHI 0
#define SM_ALO (SM_AHI + MROWS*ASTRIDE)        // 18432
#define SM_BHI (SM_ALO + MROWS*ASTRIDE)        // 36864
#define SM_BLO (SM_BHI + 64*BSTRIDE)           // 46080
#define SM_B1W2 (SM_BLO + 64*BSTRIDE)          // 55296
#define SM_TOTAL (SM_B1W2 + H*8)               // 55808

// Pre-split weights: [s][k=64][n=72], bf16 hi/lo. col 64 = skip_w[col_ids]/4, 65..71 = 0
__device__ __nv_bfloat16 g_Bhi[S * 64 * NB];
__device__ __nv_bfloat16 g_Blo[S * 64 * NB];
__device__ float2        g_b1w2[S * H];

// ------------------------------------------------------------------ helpers
__device__ __forceinline__ unsigned smem_u32(const void* p) {
    return (unsigned)__cvta_generic_to_shared(p);
}

__device__ __forceinline__ unsigned pack_pair(float a, float b, unsigned& lo) {
    __nv_bfloat16 ha = __float2bfloat16_rn(a), hb = __float2bfloat16_rn(b);
    __nv_bfloat16 la = __float2bfloat16_rn(a - __bfloat162float(ha));
    __nv_bfloat16 lb = __float2bfloat16_rn(b - __bfloat162float(hb));
    lo = ((unsigned)__bfloat16_as_ushort(lb) << 16) | (unsigned)__bfloat16_as_ushort(la);
    return ((unsigned)__bfloat16_as_ushort(hb) << 16) | (unsigned)__bfloat16_as_ushort(ha);
}

#define LDSM_X4(r0,r1,r2,r3,addr) \
    asm volatile("ldmatrix.sync.aligned.m8n8.x4.shared.b16 {%0,%1,%2,%3}, [%4];" \
        : "=r"(r0),"=r"(r1),"=r"(r2),"=r"(r3) : "r"(addr))

#define LDSM_X2T(r0,r1,addr) \
    asm volatile("ldmatrix.sync.aligned.m8n8.x2.trans.shared.b16 {%0,%1}, [%2];" \
        : "=r"(r0),"=r"(r1) : "r"(addr))

#define MMA_BF16(d,a0,a1,a2,a3,b0,b1) \
    asm volatile("mma.sync.aligned.m16n8k16.row.col.f32.bf16.bf16.f32 " \
        "{%0,%1,%2,%3}, {%4,%5,%6,%7}, {%8,%9}, {%0,%1,%2,%3};" \
        : "+f"((d)[0]),"+f"((d)[1]),"+f"((d)[2]),"+f"((d)[3]) \
        : "r"(a0),"r"(a1),"r"(a2),"r"(a3),"r"(b0),"r"(b1))

// ------------------------------------------------------------------ prep
__global__ void prep_bw(const float* __restrict__ W1,
                        const float* __restrict__ skip_w,
                        const int*   __restrict__ col_ids)
{
    int idx = blockIdx.x * blockDim.x + threadIdx.x;
    if (idx >= S * 64 * NB) return;
    int s = idx / (64 * NB);
    int rem = idx % (64 * NB);
    int k = rem / NB;
    int n = rem % NB;
    float v = 0.f;
    if (n < 64)       v = W1[(size_t)s * 4096 + (size_t)k * 64 + n];
    else if (n == 64) v = skip_w[col_ids[s * 64 + k]] * 0.25f;
    __nv_bfloat16 hi = __float2bfloat16_rn(v);
    __nv_bfloat16 lo = __float2bfloat16_rn(v - __bfloat162float(hi));
    g_Bhi[idx] = hi;
    g_Blo[idx] = lo;
}

__global__ void prep_b1w2(const float* __restrict__ b1, const float* __restrict__ W2)
{
    int idx = blockIdx.x * blockDim.x + threadIdx.x;
    if (idx < S * H) g_b1w2[idx] = make_float2(b1[idx], W2[idx]);
}

// ------------------------------------------------------------------ main
__global__ void __launch_bounds__(THREADS, 3)
hybrid_main(const float* __restrict__ x,
            const float* __restrict__ skip_b,
            const float* __restrict__ b2,
            const int*   __restrict__ col_ids,
            float* __restrict__ out)
{
    extern __shared__ char smem[];
    const int tid  = threadIdx.x;
    const int lane = tid & 31;
    const int wid  = tid >> 5;          // 0..7
    const int wrow = wid * 16;          // warp's row stripe
    const int rowbase = blockIdx.x * MROWS;

    float2* b1w2s = reinterpret_cast<float2*>(smem + SM_B1W2);

    // ldmatrix lane addresses (byte offsets into smem), constant across segments
    // A (row-major, x4): groups of 8 lanes -> (rows 0-7, rows 8-15) x (k+0, k+8)
    const int a_row = wrow + ((lane >> 3) & 1) * 8 + (lane & 7);
    const unsigned a_base_hi = smem_u32(smem + SM_AHI) + a_row * ASTRIDE + (lane >> 4) * 16;
    const unsigned a_base_lo = a_base_hi + (SM_ALO - SM_AHI);
    // B (k-major rows, x2.trans): lanes 0-15 -> rows k..k+15
    const int b_row = lane & 15;
    const unsigned b_base_hi = smem_u32(smem + SM_BHI) + b_row * BSTRIDE;
    const unsigned b_base_lo = b_base_hi + (SM_BLO - SM_BHI);

    // gather identity: thread -> (row, 32-col half)
    const int g_row  = tid >> 1;
    const int g_half = tid & 1;
    const float* xrow = x + (size_t)(rowbase + g_row) * D;
    char* g_dst_hi = smem + SM_AHI + g_row * ASTRIDE + g_half * 64;
    char* g_dst_lo = g_dst_hi + (SM_ALO - SM_AHI);

    float rowacc0 = 0.f, rowacc1 = 0.f;

    for (int s = 0; s < S; ++s) {
        __syncthreads();   // smem reusable (prev segment fully consumed)

        // ---- stage B hi/lo (18.4 KB) + b1/W2
        {
            const uint4* shi = reinterpret_cast<const uint4*>(g_Bhi) + s * (64 * BSTRIDE / 16);
            const uint4* slo = reinterpret_cast<const uint4*>(g_Blo) + s * (64 * BSTRIDE / 16);
            uint4* dhi = reinterpret_cast<uint4*>(smem + SM_BHI);
            uint4* dlo = reinterpret_cast<uint4*>(smem + SM_BLO);
            #pragma unroll
            for (int i = 0; i < 3; ++i) {          // 3*256 > 576
                int j = tid + i * THREADS;
                if (j < 64 * BSTRIDE / 16) { dhi[j] = shi[j]; dlo[j] = slo[j]; }
            }
            if (tid < H) b1w2s[tid] = g_b1w2[s * H + tid];
        }

        // ---- gather x columns + bf16 hi/lo split into A tiles
        {
            const int c0 = __ldg(&col_ids[s * 64 + g_half * 32]);
            const float4* src = reinterpret_cast<const float4*>(xrow + c0);
            #pragma unroll
            for (int i = 0; i < 4; ++i) {
                float4 fa = src[i * 2];
                float4 fb = src[i * 2 + 1];
                uint4 hv, lv;
                hv.x = pack_pair(fa.x, fa.y, lv.x);
                hv.y = pack_pair(fa.z, fa.w, lv.y);
                hv.z = pack_pair(fb.x, fb.y, lv.z);
                hv.w = pack_pair(fb.z, fb.w, lv.w);
                *reinterpret_cast<uint4*>(g_dst_hi + i * 16) = hv;
                *reinterpret_cast<uint4*>(g_dst_lo + i * 16) = lv;
            }
        }
        __syncthreads();

        // ---- 3-term split MMA: D[16x72] per warp
        float d[NT][4];
        #pragma unroll
        for (int nt = 0; nt < NT; ++nt)
            { d[nt][0] = 0.f; d[nt][1] = 0.f; d[nt][2] = 0.f; d[nt][3] = 0.f; }

        #pragma unroll
        for (int kk = 0; kk < 4; ++kk) {
            const unsigned koffA = kk * 32;      // 16 bf16 = 32 B
            unsigned ah0, ah1, ah2, ah3, al0, al1, al2, al3;
            LDSM_X4(ah0, ah1, ah2, ah3, a_base_hi + koffA);
            LDSM_X4(al0, al1, al2, al3, a_base_lo + koffA);
            const unsigned koffB = kk * 16 * BSTRIDE;
            #pragma unroll
            for (int nt = 0; nt < NT; ++nt) {
                unsigned bh0, bh1, bl0, bl1;
                LDSM_X2T(bh0, bh1, b_base_hi + koffB + nt * 16);
                LDSM_X2T(bl0, bl1, b_base_lo + koffB + nt * 16);
                MMA_BF16(d[nt], ah0, ah1, ah2, ah3, bh0, bh1);
                MMA_BF16(d[nt], ah0, ah1, ah2, ah3, bl0, bl1);
                MMA_BF16(d[nt], al0, al1, al2, al3, bh0, bh1);
            }
        }

        // ---- epilogue: relu(d+b1).W2 for h<64; raw for skip tile (cols 64..71)
        {
            float p0 = 0.f, p1 = 0.f;
            const int cbase = 2 * (lane & 3);
            #pragma unroll
            for (int nt = 0; nt < 8; ++nt) {
                const float2 bw0 = b1w2s[nt * 8 + cbase];
                const float2 bw1 = b1w2s[nt * 8 + cbase + 1];
                p0 += fmaxf(d[nt][0] + bw0.x, 0.f) * bw0.y;
                p0 += fmaxf(d[nt][1] + bw1.x, 0.f) * bw1.y;
                p1 += fmaxf(d[nt][2] + bw0.x, 0.f) * bw0.y;
                p1 += fmaxf(d[nt][3] + bw1.x, 0.f) * bw1.y;
            }
            p0 += d[8][0] + d[8][1];     // cols 65..71 are exactly zero
            p1 += d[8][2] + d[8][3];
            p0 += __shfl_xor_sync(0xffffffffu, p0, 1);
            p0 += __shfl_xor_sync(0xffffffffu, p0, 2);
            p1 += __shfl_xor_sync(0xffffffffu, p1, 1);
            p1 += __shfl_xor_sync(0xffffffffu, p1, 2);
            rowacc0 += p0;
            rowacc1 += p1;
        }
    }

    // ---- finalize
    if ((lane & 3) == 0) {
        float extras = skip_b[0];
        #pragma unroll
        for (int s = 0; s < S; ++s) extras += b2[s];
        const int r0 = rowbase + wrow + (lane >> 2);
        float v0 = rowacc0 + extras;
        float v1 = rowacc1 + extras;
        out[r0]     = fminf(fmaxf(v0, -20.0f), 20.0f);
        out[r0 + 8] = fminf(fmaxf(v1, -20.0f), 20.0f);
    }
}

// ------------------------------------------------------------------ launch
extern "C" void kernel_launch(void* const* d_in, const int* in_sizes, int n_in,
                              void* d_out, int out_size)
{
    const float* x       = (const float*)d_in[0];
    const float* skip_w  = (const float*)d_in[1];
    const float* skip_b  = (const float*)d_in[2];
    const float* W1      = (const float*)d_in[3];
    const float* b1      = (const float*)d_in[4];
    const float* W2      = (const float*)d_in[5];
    const float* b2      = (const float*)d_in[6];
    const int*   col_ids = (const int*)  d_in[7];
    float* out = (float*)d_out;

    static bool attr_set = false;
    if (!attr_set) {
        cudaFuncSetAttribute(hybrid_main,
                             cudaFuncAttributeMaxDynamicSharedMemorySize, SM_TOTAL);
        attr_set = true;
    }

    prep_bw<<<(S * 64 * NB + 255) / 256, 256>>>(W1, skip_w, col_ids);
    prep_b1w2<<<(S * H + 255) / 256, 256>>>(b1, W2);

    const int nrows = in_sizes[0] / D;   // 65536
    const int grid  = nrows / MROWS;     // 512
    hybrid_main<<<grid, THREADS, SM_TOTAL>>>(x, skip_b, b2, col_ids, out);
}

// round 4
// speedup vs baseline: 1.5354x; 1.0797x over previous
#include <cuda_runtime.h>
#include <cuda_bf16.h>
#include <cstdint>

// Problem constants
#define D 512
#define S 32
#define C 64
#define H 64
#define MROWS 128           // rows per CTA
#define THREADS 256         // 8 warps, warp = 16-row stripe
#define NB 72               // output cols: 64 h + skip col (64) + 7 zero pad
#define NT 9                // n-tiles of 8
#define ASTRIDE 144         // bytes per A row  (72 bf16; 64 used) -> ldmatrix conflict-free
#define BSTRIDE 144         // bytes per B row

#define BTILE 9216          // one B half-tile (64 rows * 144 B)
#define BBUF  (2*BTILE)     // hi + lo

// smem byte offsets
#define SM_AHI 0
#define SM_ALO (SM_AHI + MROWS*ASTRIDE)        // 18432
#define SM_B0  (SM_ALO + MROWS*ASTRIDE)        // 36864  (double-buffered: +buf*BBUF)
#define SM_B1W2 (SM_B0 + 2*BBUF)               // 73728  (all 32 segments: S*H float2)
#define SM_TOTAL (SM_B1W2 + S*H*8)             // 90112

// Pre-split weights: [s][k=64][n=72] bf16 hi/lo; col 64 = skip_w[col_ids]/4, 65..71 = 0
__device__ __nv_bfloat16 g_Bhi[S * 64 * NB];
__device__ __nv_bfloat16 g_Blo[S * 64 * NB];
__device__ float2        g_b1w2[S * H];

// ------------------------------------------------------------------ helpers
__device__ __forceinline__ unsigned smem_u32(const void* p) {
    return (unsigned)__cvta_generic_to_shared(p);
}

__device__ __forceinline__ unsigned pack_pair(float a, float b, unsigned& lo) {
    __nv_bfloat16 ha = __float2bfloat16_rn(a), hb = __float2bfloat16_rn(b);
    __nv_bfloat16 la = __float2bfloat16_rn(a - __bfloat162float(ha));
    __nv_bfloat16 lb = __float2bfloat16_rn(b - __bfloat162float(hb));
    lo = ((unsigned)__bfloat16_as_ushort(lb) << 16) | (unsigned)__bfloat16_as_ushort(la);
    return ((unsigned)__bfloat16_as_ushort(hb) << 16) | (unsigned)__bfloat16_as_ushort(ha);
}

#define LDSM_X4(r0,r1,r2,r3,addr) \
    asm volatile("ldmatrix.sync.aligned.m8n8.x4.shared.b16 {%0,%1,%2,%3}, [%4];" \
        : "=r"(r0),"=r"(r1),"=r"(r2),"=r"(r3) : "r"(addr))

// x4.trans: lanes 0-15 -> matrices 0,1 (hi), lanes 16-31 -> matrices 2,3 (lo)
#define LDSM_X4T(r0,r1,r2,r3,addr) \
    asm volatile("ldmatrix.sync.aligned.m8n8.x4.trans.shared.b16 {%0,%1,%2,%3}, [%4];" \
        : "=r"(r0),"=r"(r1),"=r"(r2),"=r"(r3) : "r"(addr))

#define MMA_BF16(d,a0,a1,a2,a3,b0,b1) \
    asm volatile("mma.sync.aligned.m16n8k16.row.col.f32.bf16.bf16.f32 " \
        "{%0,%1,%2,%3}, {%4,%5,%6,%7}, {%8,%9}, {%0,%1,%2,%3};" \
        : "+f"((d)[0]),"+f"((d)[1]),"+f"((d)[2]),"+f"((d)[3]) \
        : "r"(a0),"r"(a1),"r"(a2),"r"(a3),"r"(b0),"r"(b1))

#define CP16(dst, src) \
    asm volatile("cp.async.cg.shared.global [%0], [%1], 16;" :: "r"(dst), "l"(src))
#define CP_COMMIT() asm volatile("cp.async.commit_group;")
#define CP_WAIT0()  asm volatile("cp.async.wait_group 0;")

// ------------------------------------------------------------------ prep
__global__ void prep_bw(const float* __restrict__ W1,
                        const float* __restrict__ skip_w,
                        const int*   __restrict__ col_ids)
{
    int idx = blockIdx.x * blockDim.x + threadIdx.x;
    if (idx >= S * 64 * NB) return;
    int s = idx / (64 * NB);
    int rem = idx % (64 * NB);
    int k = rem / NB;
    int n = rem % NB;
    float v = 0.f;
    if (n < 64)       v = W1[(size_t)s * 4096 + (size_t)k * 64 + n];
    else if (n == 64) v = skip_w[col_ids[s * 64 + k]] * 0.25f;
    __nv_bfloat16 hi = __float2bfloat16_rn(v);
    __nv_bfloat16 lo = __float2bfloat16_rn(v - __bfloat162float(hi));
    g_Bhi[idx] = hi;
    g_Blo[idx] = lo;
}

__global__ void prep_b1w2(const float* __restrict__ b1, const float* __restrict__ W2)
{
    int idx = blockIdx.x * blockDim.x + threadIdx.x;
    if (idx < S * H) g_b1w2[idx] = make_float2(b1[idx], W2[idx]);
}

// ------------------------------------------------------------------ main
__global__ void __launch_bounds__(THREADS, 2)
hybrid_main(const float* __restrict__ x,
            const float* __restrict__ skip_b,
            const float* __restrict__ b2,
            const int*   __restrict__ col_ids,
            float* __restrict__ out)
{
    extern __shared__ char smem[];
    const unsigned sbase = smem_u32(smem);
    const int tid  = threadIdx.x;
    const int lane = tid & 31;
    const int wid  = tid >> 5;
    const int wrow = wid * 16;
    const int rowbase = blockIdx.x * MROWS;

    float2* b1w2s = reinterpret_cast<float2*>(smem + SM_B1W2);

    // ldmatrix lane addresses (constant across segments)
    const int a_row = wrow + ((lane >> 3) & 1) * 8 + (lane & 7);
    const unsigned a_hi = sbase + SM_AHI + a_row * ASTRIDE + (lane >> 4) * 16;
    const unsigned a_lo = a_hi + (SM_ALO - SM_AHI);
    // B x4.trans: lanes 0-15 -> hi rows, 16-31 -> lo rows
    const unsigned b_lane = sbase + SM_B0 + ((lane >> 4) ? BTILE : 0) + (lane & 15) * BSTRIDE;

    // gather identity: thread -> (row, 32-col half)
    const int g_row  = tid >> 1;
    const int g_half = tid & 1;
    const float* xrow = x + (size_t)(rowbase + g_row) * D;
    char* g_dst_hi = smem + SM_AHI + g_row * ASTRIDE + g_half * 64;
    char* g_dst_lo = g_dst_hi + (SM_ALO - SM_AHI);

    // ---------------- prologue ----------------
    // stage all b1/W2 pairs (16 KB)
    {
        const uint4* src = reinterpret_cast<const uint4*>(g_b1w2);
        uint4* dst = reinterpret_cast<uint4*>(smem + SM_B1W2);
        #pragma unroll
        for (int i = 0; i < 4; ++i) dst[tid + i * THREADS] = src[tid + i * THREADS];
    }
    // cp.async B(0) into buffer 0
    {
        const char* ghi = reinterpret_cast<const char*>(g_Bhi);
        const char* glo = reinterpret_cast<const char*>(g_Blo);
        const unsigned dhi = sbase + SM_B0;
        #pragma unroll
        for (int i = 0; i < 3; ++i) {
            int j = tid + i * THREADS;
            if (j < BTILE / 16) {
                CP16(dhi + j * 16,         ghi + j * 16);
                CP16(dhi + BTILE + j * 16, glo + j * 16);
            }
        }
        CP_COMMIT();
    }
    // register prefetch of gather for segment 0
    float4 pf[8];
    {
        const int c0 = __ldg(&col_ids[g_half * 32]);
        const float4* src = reinterpret_cast<const float4*>(xrow + c0);
        #pragma unroll
        for (int i = 0; i < 8; ++i) pf[i] = src[i];
    }

    float rowacc0 = 0.f, rowacc1 = 0.f;

    for (int s = 0; s < S; ++s) {
        const int buf = s & 1;
        __syncthreads();   // A(s-1) fully consumed; (s=0: orders b1w2 staging)

        // ---- convert prefetched gather -> A hi/lo tiles
        #pragma unroll
        for (int i = 0; i < 4; ++i) {
            float4 fa = pf[2 * i], fb = pf[2 * i + 1];
            uint4 hv, lv;
            hv.x = pack_pair(fa.x, fa.y, lv.x);
            hv.y = pack_pair(fa.z, fa.w, lv.y);
            hv.z = pack_pair(fb.x, fb.y, lv.z);
            hv.w = pack_pair(fb.z, fb.w, lv.w);
            *reinterpret_cast<uint4*>(g_dst_hi + i * 16) = hv;
            *reinterpret_cast<uint4*>(g_dst_lo + i * 16) = lv;
        }

        CP_WAIT0();        // B(s) landed (per-thread)
        __syncthreads();   // A(s) + B(s) visible to all

        // ---- prefetch next segment (B via cp.async, gather via LDG->regs)
        if (s + 1 < S) {
            const char* ghi = reinterpret_cast<const char*>(g_Bhi) + (size_t)(s + 1) * BTILE;
            const char* glo = reinterpret_cast<const char*>(g_Blo) + (size_t)(s + 1) * BTILE;
            const unsigned dhi = sbase + SM_B0 + (buf ^ 1) * BBUF;
            #pragma unroll
            for (int i = 0; i < 3; ++i) {
                int j = tid + i * THREADS;
                if (j < BTILE / 16) {
                    CP16(dhi + j * 16,         ghi + j * 16);
                    CP16(dhi + BTILE + j * 16, glo + j * 16);
                }
            }
            CP_COMMIT();
            const int c0 = __ldg(&col_ids[(s + 1) * 64 + g_half * 32]);
            const float4* src = reinterpret_cast<const float4*>(xrow + c0);
            #pragma unroll
            for (int i = 0; i < 8; ++i) pf[i] = src[i];
        }

        // ---- 3-term split MMA: D[16x72] per warp
        float d[NT][4];
        #pragma unroll
        for (int nt = 0; nt < NT; ++nt)
            { d[nt][0] = 0.f; d[nt][1] = 0.f; d[nt][2] = 0.f; d[nt][3] = 0.f; }

        const unsigned bseg = b_lane + buf * BBUF;
        #pragma unroll
        for (int kk = 0; kk < 4; ++kk) {
            unsigned ah0, ah1, ah2, ah3, al0, al1, al2, al3;
            LDSM_X4(ah0, ah1, ah2, ah3, a_hi + kk * 32);
            LDSM_X4(al0, al1, al2, al3, a_lo + kk * 32);
            const unsigned bk = bseg + kk * 16 * BSTRIDE;
            #pragma unroll
            for (int nt = 0; nt < NT; ++nt) {
                unsigned bh0, bh1, bl0, bl1;
                LDSM_X4T(bh0, bh1, bl0, bl1, bk + nt * 16);
                MMA_BF16(d[nt], ah0, ah1, ah2, ah3, bh0, bh1);
                MMA_BF16(d[nt], ah0, ah1, ah2, ah3, bl0, bl1);
                MMA_BF16(d[nt], al0, al1, al2, al3, bh0, bh1);
            }
        }

        // ---- epilogue: relu(d+b1).W2 for h<64; raw for skip tile
        {
            float p0 = 0.f, p1 = 0.f;
            const int cbase = 2 * (lane & 3);
            const float2* bw = b1w2s + s * H;
            #pragma unroll
            for (int nt = 0; nt < 8; ++nt) {
                const float2 bw0 = bw[nt * 8 + cbase];
                const float2 bw1 = bw[nt * 8 + cbase + 1];
                p0 += fmaxf(d[nt][0] + bw0.x, 0.f) * bw0.y;
                p0 += fmaxf(d[nt][1] + bw1.x, 0.f) * bw1.y;
                p1 += fmaxf(d[nt][2] + bw0.x, 0.f) * bw0.y;
                p1 += fmaxf(d[nt][3] + bw1.x, 0.f) * bw1.y;
            }
            p0 += d[8][0] + d[8][1];     // cols 65..71 exactly zero
            p1 += d[8][2] + d[8][3];
            p0 += __shfl_xor_sync(0xffffffffu, p0, 1);
            p0 += __shfl_xor_sync(0xffffffffu, p0, 2);
            p1 += __shfl_xor_sync(0xffffffffu, p1, 1);
            p1 += __shfl_xor_sync(0xffffffffu, p1, 2);
            rowacc0 += p0;
            rowacc1 += p1;
        }
    }

    // ---- finalize
    if ((lane & 3) == 0) {
        float extras = skip_b[0];
        #pragma unroll
        for (int s = 0; s < S; ++s) extras += b2[s];
        const int r0 = rowbase + wrow + (lane >> 2);
        out[r0]     = fminf(fmaxf(rowacc0 + extras, -20.0f), 20.0f);
        out[r0 + 8] = fminf(fmaxf(rowacc1 + extras, -20.0f), 20.0f);
    }
}

// ------------------------------------------------------------------ launch
extern "C" void kernel_launch(void* const* d_in, const int* in_sizes, int n_in,
                              void* d_out, int out_size)
{
    const float* x       = (const float*)d_in[0];
    const float* skip_w  = (const float*)d_in[1];
    const float* skip_b  = (const float*)d_in[2];
    const float* W1      = (const float*)d_in[3];
    const float* b1      = (const float*)d_in[4];
    const float* W2      = (const float*)d_in[5];
    const float* b2      = (const float*)d_in[6];
    const int*   col_ids = (const int*)  d_in[7];
    float* out = (float*)d_out;

    static bool attr_set = false;
    if (!attr_set) {
        cudaFuncSetAttribute(hybrid_main,
                             cudaFuncAttributeMaxDynamicSharedMemorySize, SM_TOTAL);
        attr_set = true;
    }

    prep_bw<<<(S * 64 * NB + 255) / 256, 256>>>(W1, skip_w, col_ids);
    prep_b1w2<<<(S * H + 255) / 256, 256>>>(b1, W2);

    const int nrows = in_sizes[0] / D;   // 65536
    const int grid  = nrows / MROWS;     // 512
    hybrid_main<<<grid, THREADS, SM_TOTAL>>>(x, skip_b, b2, col_ids, out);
}

// round 5
// speedup vs baseline: 1.5560x; 1.0134x over previous
#include <cuda_runtime.h>
#include <cuda_bf16.h>
#include <cstdint>

// Problem constants
#define D 512
#define S 32
#define C 64
#define H 64
#define MROWS 128           // rows per CTA
#define THREADS 256         // 8 warps, warp = 16-row stripe
#define NB 72               // B storage cols (64 used + pad for 144B stride)
#define NT 8                // n-tiles of 8 (h = 64)
#define ASTRIDE 144         // bytes per A row -> ldmatrix conflict-free
#define BSTRIDE 144         // bytes per B row

#define BTILE 9216          // one B half-tile (64 rows * 144 B)
#define BBUF  (2*BTILE)     // hi + lo

// smem byte offsets
#define SM_AHI 0
#define SM_ALO (SM_AHI + MROWS*ASTRIDE)        // 18432
#define SM_B0  (SM_ALO + MROWS*ASTRIDE)        // 36864  (+buf*BBUF)
#define SM_B1W2 (SM_B0 + 2*BBUF)               // 73728  S*H float2
#define SM_SWG  (SM_B1W2 + S*H*8)              // 90112  S*64 float
#define SM_TOTAL (SM_SWG + S*64*4)             // 98304

// Pre-split weights: [s][k=64][n=72] bf16 hi/lo (cols >=64 zero/pad)
__device__ __nv_bfloat16 g_Bhi[S * 64 * NB];
__device__ __nv_bfloat16 g_Blo[S * 64 * NB];
__device__ float2        g_b1w2[S * H];
__device__ float         g_swg[S * 64];    // skip_w[col_ids]/4
__device__ float         g_extras;         // skip_b + sum(b2)

// ------------------------------------------------------------------ helpers
__device__ __forceinline__ unsigned smem_u32(const void* p) {
    return (unsigned)__cvta_generic_to_shared(p);
}

__device__ __forceinline__ unsigned pack_pair(float a, float b, unsigned& lo) {
    __nv_bfloat16 ha = __float2bfloat16_rn(a), hb = __float2bfloat16_rn(b);
    __nv_bfloat16 la = __float2bfloat16_rn(a - __bfloat162float(ha));
    __nv_bfloat16 lb = __float2bfloat16_rn(b - __bfloat162float(hb));
    lo = ((unsigned)__bfloat16_as_ushort(lb) << 16) | (unsigned)__bfloat16_as_ushort(la);
    return ((unsigned)__bfloat16_as_ushort(hb) << 16) | (unsigned)__bfloat16_as_ushort(ha);
}

#define LDSM_X4(r0,r1,r2,r3,addr) \
    asm volatile("ldmatrix.sync.aligned.m8n8.x4.shared.b16 {%0,%1,%2,%3}, [%4];" \
        : "=r"(r0),"=r"(r1),"=r"(r2),"=r"(r3) : "r"(addr))

// x4.trans: lanes 0-15 -> matrices 0,1 (hi tile), lanes 16-31 -> matrices 2,3 (lo tile)
#define LDSM_X4T(r0,r1,r2,r3,addr) \
    asm volatile("ldmatrix.sync.aligned.m8n8.x4.trans.shared.b16 {%0,%1,%2,%3}, [%4];" \
        : "=r"(r0),"=r"(r1),"=r"(r2),"=r"(r3) : "r"(addr))

#define MMA_BF16(d,a0,a1,a2,a3,b0,b1) \
    asm volatile("mma.sync.aligned.m16n8k16.row.col.f32.bf16.bf16.f32 " \
        "{%0,%1,%2,%3}, {%4,%5,%6,%7}, {%8,%9}, {%0,%1,%2,%3};" \
        : "+f"((d)[0]),"+f"((d)[1]),"+f"((d)[2]),"+f"((d)[3]) \
        : "r"(a0),"r"(a1),"r"(a2),"r"(a3),"r"(b0),"r"(b1))

#define CP16(dst, src) \
    asm volatile("cp.async.cg.shared.global [%0], [%1], 16;" :: "r"(dst), "l"(src))
#define CP_COMMIT() asm volatile("cp.async.commit_group;")
#define CP_WAIT0()  asm volatile("cp.async.wait_group 0;")

// ------------------------------------------------------------------ fused prep
__global__ void prep_all(const float* __restrict__ W1,
                         const float* __restrict__ skip_w,
                         const float* __restrict__ skip_b,
                         const float* __restrict__ b1,
                         const float* __restrict__ W2,
                         const float* __restrict__ b2,
                         const int*   __restrict__ col_ids)
{
    int idx = blockIdx.x * blockDim.x + threadIdx.x;
    if (idx < S * 64 * NB) {
        int s = idx / (64 * NB);
        int rem = idx % (64 * NB);
        int k = rem / NB;
        int n = rem % NB;
        float v = (n < 64) ? W1[(size_t)s * 4096 + (size_t)k * 64 + n] : 0.f;
        __nv_bfloat16 hi = __float2bfloat16_rn(v);
        __nv_bfloat16 lo = __float2bfloat16_rn(v - __bfloat162float(hi));
        g_Bhi[idx] = hi;
        g_Blo[idx] = lo;
        return;
    }
    int r = idx - S * 64 * NB;
    if (r < S * H) {
        g_b1w2[r] = make_float2(b1[r], W2[r]);
        return;
    }
    r -= S * H;
    if (r < S * 64) {
        g_swg[r] = skip_w[col_ids[r]] * 0.25f;
        return;
    }
    if (r == S * 64) {
        float e = skip_b[0];
        for (int s = 0; s < S; ++s) e += b2[s];
        g_extras = e;
    }
}

// ------------------------------------------------------------------ main
__global__ void __launch_bounds__(THREADS, 2)
hybrid_main(const float* __restrict__ x,
            const int*   __restrict__ col_ids,
            float* __restrict__ out)
{
    extern __shared__ char smem[];
    const unsigned sbase = smem_u32(smem);
    const int tid  = threadIdx.x;
    const int lane = tid & 31;
    const int wid  = tid >> 5;
    const int wrow = wid * 16;
    const int rowbase = blockIdx.x * MROWS;

    float2* b1w2s = reinterpret_cast<float2*>(smem + SM_B1W2);
    const float* swg_s = reinterpret_cast<const float*>(smem + SM_SWG);

    // ldmatrix lane addresses (constant across segments)
    const int a_row = wrow + ((lane >> 3) & 1) * 8 + (lane & 7);
    const unsigned a_hi = sbase + SM_AHI + a_row * ASTRIDE + (lane >> 4) * 16;
    const unsigned a_lo = a_hi + (SM_ALO - SM_AHI);
    const unsigned b_lane = sbase + SM_B0 + ((lane >> 4) ? BTILE : 0) + (lane & 15) * BSTRIDE;

    // gather identity: thread -> (row, 32-col half)
    const int g_row  = tid >> 1;
    const int g_half = tid & 1;
    const float* xrow = x + (size_t)(rowbase + g_row) * D;
    char* g_dst_hi = smem + SM_AHI + g_row * ASTRIDE + g_half * 64;
    char* g_dst_lo = g_dst_hi + (SM_ALO - SM_AHI);

    // ---------------- prologue ----------------
    // stage b1/W2 pairs (16 KB) + gathered skip weights (8 KB)
    {
        const uint4* src = reinterpret_cast<const uint4*>(g_b1w2);
        uint4* dst = reinterpret_cast<uint4*>(smem + SM_B1W2);
        #pragma unroll
        for (int i = 0; i < 4; ++i) dst[tid + i * THREADS] = src[tid + i * THREADS];
        const uint4* src2 = reinterpret_cast<const uint4*>(g_swg);
        uint4* dst2 = reinterpret_cast<uint4*>(smem + SM_SWG);
        #pragma unroll
        for (int i = 0; i < 2; ++i) dst2[tid + i * THREADS] = src2[tid + i * THREADS];
    }
    // cp.async B(0) into buffer 0
    {
        const char* ghi = reinterpret_cast<const char*>(g_Bhi);
        const char* glo = reinterpret_cast<const char*>(g_Blo);
        const unsigned dhi = sbase + SM_B0;
        #pragma unroll
        for (int i = 0; i < 3; ++i) {
            int j = tid + i * THREADS;
            if (j < BTILE / 16) {
                CP16(dhi + j * 16,         ghi + j * 16);
                CP16(dhi + BTILE + j * 16, glo + j * 16);
            }
        }
        CP_COMMIT();
    }
    // register prefetch of gather for segment 0
    float4 pf[8];
    {
        const int c0 = __ldg(&col_ids[g_half * 32]);
        const float4* src = reinterpret_cast<const float4*>(xrow + c0);
        #pragma unroll
        for (int i = 0; i < 8; ++i) pf[i] = src[i];
    }

    float rowacc0 = 0.f, rowacc1 = 0.f, skipacc = 0.f;

    for (int s = 0; s < S; ++s) {
        const int buf = s & 1;
        __syncthreads();   // A(s-1) fully consumed; s=0: orders prologue staging

        // ---- convert prefetched gather -> A hi/lo tiles, + fp32 skip dot
        {
            const float4* sw4 = reinterpret_cast<const float4*>(swg_s + s * 64 + g_half * 32);
            float sk = 0.f;
            #pragma unroll
            for (int i = 0; i < 4; ++i) {
                float4 fa = pf[2 * i], fb = pf[2 * i + 1];
                float4 wa = sw4[2 * i], wb = sw4[2 * i + 1];
                sk += fa.x * wa.x + fa.y * wa.y + fa.z * wa.z + fa.w * wa.w;
                sk += fb.x * wb.x + fb.y * wb.y + fb.z * wb.z + fb.w * wb.w;
                uint4 hv, lv;
                hv.x = pack_pair(fa.x, fa.y, lv.x);
                hv.y = pack_pair(fa.z, fa.w, lv.y);
                hv.z = pack_pair(fb.x, fb.y, lv.z);
                hv.w = pack_pair(fb.z, fb.w, lv.w);
                *reinterpret_cast<uint4*>(g_dst_hi + i * 16) = hv;
                *reinterpret_cast<uint4*>(g_dst_lo + i * 16) = lv;
            }
            skipacc += sk;
        }

        CP_WAIT0();        // B(s) landed (per-thread)
        __syncthreads();   // A(s) + B(s) visible to all

        // ---- prefetch next segment (B via cp.async, gather via LDG->regs)
        if (s + 1 < S) {
            const char* ghi = reinterpret_cast<const char*>(g_Bhi) + (size_t)(s + 1) * BTILE;
            const char* glo = reinterpret_cast<const char*>(g_Blo) + (size_t)(s + 1) * BTILE;
            const unsigned dhi = sbase + SM_B0 + (buf ^ 1) * BBUF;
            #pragma unroll
            for (int i = 0; i < 3; ++i) {
                int j = tid + i * THREADS;
                if (j < BTILE / 16) {
                    CP16(dhi + j * 16,         ghi + j * 16);
                    CP16(dhi + BTILE + j * 16, glo + j * 16);
                }
            }
            CP_COMMIT();
            const int c0 = __ldg(&col_ids[(s + 1) * 64 + g_half * 32]);
            const float4* src = reinterpret_cast<const float4*>(xrow + c0);
            #pragma unroll
            for (int i = 0; i < 8; ++i) pf[i] = src[i];
        }

        // ---- 3-term split MMA: D[16x64] per warp
        float d[NT][4];
        #pragma unroll
        for (int nt = 0; nt < NT; ++nt)
            { d[nt][0] = 0.f; d[nt][1] = 0.f; d[nt][2] = 0.f; d[nt][3] = 0.f; }

        const unsigned bseg = b_lane + buf * BBUF;
        #pragma unroll
        for (int kk = 0; kk < 4; ++kk) {
            unsigned ah0, ah1, ah2, ah3, al0, al1, al2, al3;
            LDSM_X4(ah0, ah1, ah2, ah3, a_hi + kk * 32);
            LDSM_X4(al0, al1, al2, al3, a_lo + kk * 32);
            const unsigned bk = bseg + kk * 16 * BSTRIDE;
            #pragma unroll
            for (int nt = 0; nt < NT; ++nt) {
                unsigned bh0, bh1, bl0, bl1;
                LDSM_X4T(bh0, bh1, bl0, bl1, bk + nt * 16);
                MMA_BF16(d[nt], ah0, ah1, ah2, ah3, bh0, bh1);
                MMA_BF16(d[nt], ah0, ah1, ah2, ah3, bl0, bl1);
                MMA_BF16(d[nt], al0, al1, al2, al3, bh0, bh1);
            }
        }

        // ---- epilogue: relu(d+b1).W2
        {
            float p0 = 0.f, p1 = 0.f;
            const int cbase = 2 * (lane & 3);
            const float2* bw = b1w2s + s * H;
            #pragma unroll
            for (int nt = 0; nt < NT; ++nt) {
                const float2 bw0 = bw[nt * 8 + cbase];
                const float2 bw1 = bw[nt * 8 + cbase + 1];
                p0 += fmaxf(d[nt][0] + bw0.x, 0.f) * bw0.y;
                p0 += fmaxf(d[nt][1] + bw1.x, 0.f) * bw1.y;
                p1 += fmaxf(d[nt][2] + bw0.x, 0.f) * bw0.y;
                p1 += fmaxf(d[nt][3] + bw1.x, 0.f) * bw1.y;
            }
            p0 += __shfl_xor_sync(0xffffffffu, p0, 1);
            p0 += __shfl_xor_sync(0xffffffffu, p0, 2);
            p1 += __shfl_xor_sync(0xffffffffu, p1, 1);
            p1 += __shfl_xor_sync(0xffffffffu, p1, 2);
            rowacc0 += p0;
            rowacc1 += p1;
        }
    }

    // ---- finalize: combine skip halves via smem, then write
    __syncthreads();
    {
        float sk = skipacc + __shfl_xor_sync(0xffffffffu, skipacc, 1);
        if (g_half == 0) reinterpret_cast<float*>(smem)[g_row] = sk;
    }
    __syncthreads();

    if ((lane & 3) == 0) {
        const float* skp = reinterpret_cast<const float*>(smem);
        const float extras = g_extras;
        const int lr = wrow + (lane >> 2);
        float v0 = rowacc0 + extras + skp[lr];
        float v1 = rowacc1 + extras + skp[lr + 8];
        out[rowbase + lr]     = fminf(fmaxf(v0, -20.0f), 20.0f);
        out[rowbase + lr + 8] = fminf(fmaxf(v1, -20.0f), 20.0f);
    }
}

// ------------------------------------------------------------------ launch
extern "C" void kernel_launch(void* const* d_in, const int* in_sizes, int n_in,
                              void* d_out, int out_size)
{
    const float* x       = (const float*)d_in[0];
    const float* skip_w  = (const float*)d_in[1];
    const float* skip_b  = (const float*)d_in[2];
    const float* W1      = (const float*)d_in[3];
    const float* b1      = (const float*)d_in[4];
    const float* W2      = (const float*)d_in[5];
    const float* b2      = (const float*)d_in[6];
    const int*   col_ids = (const int*)  d_in[7];
    float* out = (float*)d_out;

    static bool attr_set = false;
    if (!attr_set) {
        cudaFuncSetAttribute(hybrid_main,
                             cudaFuncAttributeMaxDynamicSharedMemorySize, SM_TOTAL);
        attr_set = true;
    }

    const int prep_items = S * 64 * NB + S * H + S * 64 + 1;
    prep_all<<<(prep_items + 255) / 256, 256>>>(W1, skip_w, skip_b, b1, W2, b2, col_ids);

    const int nrows = in_sizes[0] / D;   // 65536
    const int grid  = nrows / MROWS;     // 512
    hybrid_main<<<grid, THREADS, SM_TOTAL>>>(x, col_ids, out);
}

// round 7
// speedup vs baseline: 1.9202x; 1.2340x over previous
#include <cuda_runtime.h>
#include <cuda_fp16.h>
#include <cstdint>

// Problem constants
#define D 512
#define S 32
#define H 64
#define MROWS 256           // rows per CTA
#define THREADS 256         // 8 warps, warp = 32 rows x 64 n
#define ASTRIDE 144         // bytes per A row (64 fp16 + pad) -> conflict-free ldmatrix
#define BSTRIDE 144         // bytes per B n-row (64 fp16 k + pad)
#define BTILE (64*BSTRIDE)  // 9216 B (single fp16 W tile)

// smem byte offsets
#define SM_AHI 0
#define SM_ALO (SM_AHI + MROWS*ASTRIDE)   // 36864
#define SM_B0  (SM_ALO + MROWS*ASTRIDE)   // 73728 (+buf*BTILE, double buffered)
#define SM_SKP (SM_B0 + 2*BTILE)          // 92160 (256 floats)
#define SM_TOTAL (SM_SKP + MROWS*4)       // 93184

// W1 pre-rounded fp16, n-major: [s][n=64][k=72pad]
__device__ __half  g_Bh[S * 64 * 72];
__device__ float2  g_b1w2[S * H];
__device__ float   g_swg[S * 64];   // skip_w[col_ids]/4
__device__ float   g_extras;        // skip_b + sum(b2)

// ------------------------------------------------------------------ helpers
__device__ __forceinline__ unsigned smem_u32(const void* p) {
    return (unsigned)__cvta_generic_to_shared(p);
}

// fp16 hi/lo split of two floats, packed
__device__ __forceinline__ unsigned pack_pair(float a, float b, unsigned& lo) {
    __half ha = __float2half_rn(a), hb = __float2half_rn(b);
    __half la = __float2half_rn(a - __half2float(ha));
    __half lb = __float2half_rn(b - __half2float(hb));
    lo = ((unsigned)__half_as_ushort(lb) << 16) | (unsigned)__half_as_ushort(la);
    return ((unsigned)__half_as_ushort(hb) << 16) | (unsigned)__half_as_ushort(ha);
}

#define LDSM_X4(r0,r1,r2,r3,addr) \
    asm volatile("ldmatrix.sync.aligned.m8n8.x4.shared.b16 {%0,%1,%2,%3}, [%4];" \
        : "=r"(r0),"=r"(r1),"=r"(r2),"=r"(r3) : "r"(addr))

#define MMA_F16(d,a0,a1,a2,a3,b0,b1) \
    asm volatile("mma.sync.aligned.m16n8k16.row.col.f32.f16.f16.f32 " \
        "{%0,%1,%2,%3}, {%4,%5,%6,%7}, {%8,%9}, {%0,%1,%2,%3};" \
        : "+f"((d)[0]),"+f"((d)[1]),"+f"((d)[2]),"+f"((d)[3]) \
        : "r"(a0),"r"(a1),"r"(a2),"r"(a3),"r"(b0),"r"(b1))

#define CP16(dst, src) \
    asm volatile("cp.async.cg.shared.global [%0], [%1], 16;" :: "r"(dst), "l"(src))
#define CP_COMMIT() asm volatile("cp.async.commit_group;")
#define CP_WAIT0()  asm volatile("cp.async.wait_group 0;")

// ------------------------------------------------------------------ fused prep
__global__ void prep_all(const float* __restrict__ W1,
                         const float* __restrict__ skip_w,
                         const float* __restrict__ skip_b,
                         const float* __restrict__ b1,
                         const float* __restrict__ W2,
                         const float* __restrict__ b2,
                         const int*   __restrict__ col_ids)
{
    int idx = blockIdx.x * blockDim.x + threadIdx.x;
    if (idx < S * 64 * 72) {
        int s = idx / (64 * 72);
        int rem = idx % (64 * 72);
        int n = rem / 72;           // h index (B row, n-major)
        int k = rem % 72;           // c index
        float v = (k < 64) ? W1[(size_t)s * 4096 + (size_t)k * 64 + n] : 0.f;
        g_Bh[idx] = __float2half_rn(v);
        return;
    }
    int r = idx - S * 64 * 72;
    if (r < S * H) { g_b1w2[r] = make_float2(b1[r], W2[r]); return; }
    r -= S * H;
    if (r < S * 64) { g_swg[r] = skip_w[col_ids[r]] * 0.25f; return; }
    if (r == S * 64) {
        float e = skip_b[0];
        for (int s = 0; s < S; ++s) e += b2[s];
        g_extras = e;
    }
}

// ------------------------------------------------------------------ main
__global__ void __launch_bounds__(THREADS, 2)
hybrid_main(const float* __restrict__ x,
            const int*   __restrict__ col_ids,
            float* __restrict__ out)
{
    extern __shared__ char smem[];
    const unsigned sbase = smem_u32(smem);
    const int tid  = threadIdx.x;
    const int lane = tid & 31;
    const int wid  = tid >> 5;
    const int rowbase = blockIdx.x * MROWS;

    // A ldmatrix lane address (mt tile offset = 16*ASTRIDE = 2304)
    const int a_row = wid * 32 + ((lane >> 3) & 1) * 8 + (lane & 7);
    const unsigned a_hi = sbase + SM_AHI + a_row * ASTRIDE + (lane >> 4) * 16;
    const unsigned a_lo = a_hi + (SM_ALO - SM_AHI);

    // B ldmatrix (non-trans x4, n-major rows):
    // group g=lane>>3: n = (g>>1)*8 + (lane&7), koff = (g&1)*16
    const int bg = lane >> 3;
    const unsigned b_base = sbase + SM_B0
        + (((bg >> 1) * 8) + (lane & 7)) * BSTRIDE + (bg & 1) * 16;

    // gather identity: thread -> (row pair, 32-col half)
    const int g_row  = tid >> 1;         // 0..127; second row = +128
    const int g_half = tid & 1;
    const float* xrow1 = x + (size_t)(rowbase + g_row) * D;
    const float* xrow2 = xrow1 + (size_t)128 * D;
    char* dst1_hi = smem + SM_AHI + g_row * ASTRIDE + g_half * 64;
    char* dst2_hi = dst1_hi + 128 * ASTRIDE;

    // ---------------- prologue: cp.async B(0) ----------------
    {
        const char* gb = reinterpret_cast<const char*>(g_Bh);
        const unsigned db = sbase + SM_B0;
        #pragma unroll
        for (int i = 0; i < 3; ++i) {
            int j = tid + i * THREADS;
            if (j < BTILE / 16) CP16(db + j * 16, gb + j * 16);
        }
        CP_COMMIT();
    }

    float rowacc[2][2] = {{0.f, 0.f}, {0.f, 0.f}};
    float skip1 = 0.f, skip2 = 0.f;
    int cid = col_ids[g_half * 32];   // column base for current segment

    for (int s = 0; s < S; ++s) {
        const int buf = s & 1;
        __syncthreads();   // A(s-1) fully consumed by all warps

        // ---- gather + fp16 hi/lo convert + fp32 skip dots (inline LDG)
        {
            const float4* sw4 = reinterpret_cast<const float4*>(g_swg + s * 64 + g_half * 32);
            // row 1
            {
                const float4* src = reinterpret_cast<const float4*>(xrow1 + cid);
                float sk = 0.f;
                #pragma unroll
                for (int i = 0; i < 4; ++i) {
                    float4 fa = src[2*i], fb = src[2*i+1];
                    float4 wa = sw4[2*i], wb = sw4[2*i+1];
                    sk += fa.x*wa.x + fa.y*wa.y + fa.z*wa.z + fa.w*wa.w;
                    sk += fb.x*wb.x + fb.y*wb.y + fb.z*wb.z + fb.w*wb.w;
                    uint4 hv, lv;
                    hv.x = pack_pair(fa.x, fa.y, lv.x);
                    hv.y = pack_pair(fa.z, fa.w, lv.y);
                    hv.z = pack_pair(fb.x, fb.y, lv.z);
                    hv.w = pack_pair(fb.z, fb.w, lv.w);
                    *reinterpret_cast<uint4*>(dst1_hi + i * 16) = hv;
                    *reinterpret_cast<uint4*>(dst1_hi + (SM_ALO - SM_AHI) + i * 16) = lv;
                }
                skip1 += sk;
            }
            // row 2
            {
                const float4* src = reinterpret_cast<const float4*>(xrow2 + cid);
                float sk = 0.f;
                #pragma unroll
                for (int i = 0; i < 4; ++i) {
                    float4 fa = src[2*i], fb = src[2*i+1];
                    float4 wa = sw4[2*i], wb = sw4[2*i+1];
                    sk += fa.x*wa.x + fa.y*wa.y + fa.z*wa.z + fa.w*wa.w;
                    sk += fb.x*wb.x + fb.y*wb.y + fb.z*wb.z + fb.w*wb.w;
                    uint4 hv, lv;
                    hv.x = pack_pair(fa.x, fa.y, lv.x);
                    hv.y = pack_pair(fa.z, fa.w, lv.y);
                    hv.z = pack_pair(fb.x, fb.y, lv.z);
                    hv.w = pack_pair(fb.z, fb.w, lv.w);
                    *reinterpret_cast<uint4*>(dst2_hi + i * 16) = hv;
                    *reinterpret_cast<uint4*>(dst2_hi + (SM_ALO - SM_AHI) + i * 16) = lv;
                }
                skip2 += sk;
            }
        }

        CP_WAIT0();        // B(s) landed (only outstanding group)
        __syncthreads();   // A(s) + B(s) visible to all

        // ---- prefetch B(s+1) into other buffer; advance col base
        if (s + 1 < S) {
            const char* gb = reinterpret_cast<const char*>(g_Bh) + (size_t)(s + 1) * BTILE;
            const unsigned db = sbase + SM_B0 + (buf ^ 1) * BTILE;
            #pragma unroll
            for (int i = 0; i < 3; ++i) {
                int j = tid + i * THREADS;
                if (j < BTILE / 16) CP16(db + j * 16, gb + j * 16);
            }
            CP_COMMIT();
            cid = col_ids[(s + 1) * 64 + g_half * 32];
        }

        // ---- 2-term split MMA: D[32x64] per warp
        float d[2][8][4];
        #pragma unroll
        for (int mt = 0; mt < 2; ++mt)
            #pragma unroll
            for (int nt = 0; nt < 8; ++nt)
                { d[mt][nt][0]=0.f; d[mt][nt][1]=0.f; d[mt][nt][2]=0.f; d[mt][nt][3]=0.f; }

        const unsigned bseg = b_base + buf * BTILE;
        #pragma unroll
        for (int kk = 0; kk < 4; ++kk) {
            unsigned ah[2][4], al[2][4];
            #pragma unroll
            for (int mt = 0; mt < 2; ++mt) {
                LDSM_X4(ah[mt][0], ah[mt][1], ah[mt][2], ah[mt][3], a_hi + mt * 2304 + kk * 32);
                LDSM_X4(al[mt][0], al[mt][1], al[mt][2], al[mt][3], a_lo + mt * 2304 + kk * 32);
            }
            #pragma unroll
            for (int ntp = 0; ntp < 4; ++ntp) {
                unsigned bh0, bh1, bh2, bh3;
                LDSM_X4(bh0, bh1, bh2, bh3, bseg + ntp * 2304 + kk * 32);
                #pragma unroll
                for (int mt = 0; mt < 2; ++mt) {
                    MMA_F16(d[mt][2*ntp],   ah[mt][0],ah[mt][1],ah[mt][2],ah[mt][3], bh0, bh1);
                    MMA_F16(d[mt][2*ntp],   al[mt][0],al[mt][1],al[mt][2],al[mt][3], bh0, bh1);
                    MMA_F16(d[mt][2*ntp+1], ah[mt][0],ah[mt][1],ah[mt][2],ah[mt][3], bh2, bh3);
                    MMA_F16(d[mt][2*ntp+1], al[mt][0],al[mt][1],al[mt][2],al[mt][3], bh2, bh3);
                }
            }
        }

        // ---- epilogue: relu(d+b1).W2 (fp32 params from global), quad reduce
        {
            const float2* bw = g_b1w2 + s * H;
            const int cbase = 2 * (lane & 3);
            #pragma unroll
            for (int mt = 0; mt < 2; ++mt) {
                float p0 = 0.f, p1 = 0.f;
                #pragma unroll
                for (int nt = 0; nt < 8; ++nt) {
                    const float2 bw0 = bw[nt * 8 + cbase];
                    const float2 bw1 = bw[nt * 8 + cbase + 1];
                    p0 += fmaxf(d[mt][nt][0] + bw0.x, 0.f) * bw0.y;
                    p0 += fmaxf(d[mt][nt][1] + bw1.x, 0.f) * bw1.y;
                    p1 += fmaxf(d[mt][nt][2] + bw0.x, 0.f) * bw0.y;
                    p1 += fmaxf(d[mt][nt][3] + bw1.x, 0.f) * bw1.y;
                }
                p0 += __shfl_xor_sync(0xffffffffu, p0, 1);
                p0 += __shfl_xor_sync(0xffffffffu, p0, 2);
                p1 += __shfl_xor_sync(0xffffffffu, p1, 1);
                p1 += __shfl_xor_sync(0xffffffffu, p1, 2);
                rowacc[mt][0] += p0;
                rowacc[mt][1] += p1;
            }
        }
    }

    // ---- finalize: combine skip halves via smem, then write
    {
        float* skp = reinterpret_cast<float*>(smem + SM_SKP);
        float s1 = skip1 + __shfl_xor_sync(0xffffffffu, skip1, 1);
        float s2 = skip2 + __shfl_xor_sync(0xffffffffu, skip2, 1);
        if (g_half == 0) { skp[g_row] = s1; skp[g_row + 128] = s2; }
    }
    __syncthreads();

    if ((lane & 3) == 0) {
        const float* skp = reinterpret_cast<const float*>(smem + SM_SKP);
        const float extras = g_extras;
        #pragma unroll
        for (int mt = 0; mt < 2; ++mt) {
            const int lr = wid * 32 + mt * 16 + (lane >> 2);
            float v0 = rowacc[mt][0] + extras + skp[lr];
            float v1 = rowacc[mt][1] + extras + skp[lr + 8];
            out[rowbase + lr]     = fminf(fmaxf(v0, -20.0f), 20.0f);
            out[rowbase + lr + 8] = fminf(fmaxf(v1, -20.0f), 20.0f);
        }
    }
}

// ------------------------------------------------------------------ launch
extern "C" void kernel_launch(void* const* d_in, const int* in_sizes, int n_in,
                              void* d_out, int out_size)
{
    const float* x       = (const float*)d_in[0];
    const float* skip_w  = (const float*)d_in[1];
    const float* skip_b  = (const float*)d_in[2];
    const float* W1      = (const float*)d_in[3];
    const float* b1      = (const float*)d_in[4];
    const float* W2      = (const float*)d_in[5];
    const float* b2      = (const float*)d_in[6];
    const int*   col_ids = (const int*)  d_in[7];
    float* out = (float*)d_out;

    static bool attr_set = false;
    if (!attr_set) {
        cudaFuncSetAttribute(hybrid_main,
                             cudaFuncAttributeMaxDynamicSharedMemorySize, SM_TOTAL);
        attr_set = true;
    }

    const int prep_items = S * 64 * 72 + S * H + S * 64 + 1;
    prep_all<<<(prep_items + 255) / 256, 256>>>(W1, skip_w, skip_b, b1, W2, b2, col_ids);

    const int nrows = in_sizes[0] / D;   // 65536
    const int grid  = nrows / MROWS;     // 256
    hybrid_main<<<grid, THREADS, SM_TOTAL>>>(x, col_ids, out);
}